// round 2
// baseline (speedup 1.0000x reference)
#include <cuda_runtime.h>
#include <math.h>

// ---------------------------------------------------------------------------
// DisentangledHierarchicalEncoder — fp32 SIMT baseline
//
// Pipeline (all on default stream, graph-capturable, no allocations):
//   1. rownorm(content)  -> g_invc            2. rownorm(text) -> g_invt
//   3. L1c: relu(invc*(Xc@W1c^T)+b)  [50000,1024]   (scratch g_h1)
//   4. L2c: relu(h1@W2c^T+b)         [50000,256]    (scratch g_h2)
//   5. L3c: h2@W3c^T+b               [50000,64]     (g_cemb)
//   6-8. same for text (reusing g_h1/g_h2)          (g_temb)
//   9. cf:  Xcf@cfW^T+b              [50000,64]     (g_cfemb)
//  10. fused per-token: gather 4 modals, l2norm, LayerNorm, q/k,
//      softmax, and out = (sum_n c_n * xn_n) @ Wv^T   (V never materialized)
// ---------------------------------------------------------------------------

#define NUM_ITEM   50000
#define N_TOKENS   (1024 * 50)
#define TOK_PER_BLOCK 32

// ------------------------- device scratch (static) -------------------------
__device__ float g_h1[50000 * 1024];   // 204.8 MB (content h1, reused for text h1)
__device__ float g_h2[50000 * 256];    // 51.2 MB
__device__ float g_cemb[50000 * 64];
__device__ float g_temb[50000 * 64];
__device__ float g_cfemb[50000 * 64];
__device__ float g_invc[50000];
__device__ float g_invt[50000];

// ------------------------- inverse L2 row norm ------------------------------
__global__ void rownorm_kernel(const float* __restrict__ X, int K, int M,
                               float* __restrict__ inv)
{
    int row = blockIdx.x;
    if (row >= M) return;
    const float4* x4 = reinterpret_cast<const float4*>(X + (size_t)row * K);
    int K4 = K >> 2;
    float s = 0.f;
    for (int i = threadIdx.x; i < K4; i += blockDim.x) {
        float4 v = x4[i];
        s += v.x * v.x + v.y * v.y + v.z * v.z + v.w * v.w;
    }
#pragma unroll
    for (int o = 16; o > 0; o >>= 1) s += __shfl_xor_sync(0xffffffffu, s, o);
    __shared__ float red[4];
    int w = threadIdx.x >> 5;
    if ((threadIdx.x & 31) == 0) red[w] = s;
    __syncthreads();
    if (threadIdx.x == 0) {
        float t = red[0] + red[1] + red[2] + red[3];
        inv[row] = 1.0f / fmaxf(sqrtf(t), 1e-12f);
    }
}

// ------------------------- tiled SGEMM: C = act(scale * (A @ W^T) + b) ------
// A: [M,K] row-major.  W: [N,K] row-major (PyTorch Linear layout -> NT gemm).
template <int BM, int BN, int BK, int TM, int TN, bool RELU>
__global__ void __launch_bounds__((BM / TM) * (BN / TN))
sgemm_nt(int M, int N, int K,
         const float* __restrict__ A,
         const float* __restrict__ W,
         const float* __restrict__ bias,
         const float* __restrict__ rowscale,   // may be nullptr
         float* __restrict__ C)
{
    constexpr int NT = (BM / TM) * (BN / TN);
    constexpr int KQ = BK / 4;
    __shared__ float As[BK][BM];
    __shared__ float Ws[BK][BN];

    const int tid  = threadIdx.x;
    const int bm   = blockIdx.y * BM;
    const int bn   = blockIdx.x * BN;
    const int row0 = (tid / (BN / TN)) * TM;
    const int col0 = (tid % (BN / TN)) * TN;

    float acc[TM][TN];
#pragma unroll
    for (int i = 0; i < TM; ++i)
#pragma unroll
        for (int j = 0; j < TN; ++j) acc[i][j] = 0.f;

    for (int k0 = 0; k0 < K; k0 += BK) {
        for (int i = tid; i < BM * KQ; i += NT) {
            int r = i / KQ, q = i % KQ;
            int gr = bm + r;
            float4 v = make_float4(0.f, 0.f, 0.f, 0.f);
            if (gr < M)
                v = *reinterpret_cast<const float4*>(&A[(size_t)gr * K + k0 + 4 * q]);
            As[4 * q + 0][r] = v.x; As[4 * q + 1][r] = v.y;
            As[4 * q + 2][r] = v.z; As[4 * q + 3][r] = v.w;
        }
        for (int i = tid; i < BN * KQ; i += NT) {
            int r = i / KQ, q = i % KQ;
            int gr = bn + r;
            float4 v = make_float4(0.f, 0.f, 0.f, 0.f);
            if (gr < N)
                v = *reinterpret_cast<const float4*>(&W[(size_t)gr * K + k0 + 4 * q]);
            Ws[4 * q + 0][r] = v.x; Ws[4 * q + 1][r] = v.y;
            Ws[4 * q + 2][r] = v.z; Ws[4 * q + 3][r] = v.w;
        }
        __syncthreads();
#pragma unroll
        for (int k = 0; k < BK; ++k) {
            float ra[TM], rw[TN];
#pragma unroll
            for (int i = 0; i < TM; i += 4) {
                float4 v = *reinterpret_cast<const float4*>(&As[k][row0 + i]);
                ra[i] = v.x; ra[i + 1] = v.y; ra[i + 2] = v.z; ra[i + 3] = v.w;
            }
#pragma unroll
            for (int j = 0; j < TN; j += 4) {
                float4 v = *reinterpret_cast<const float4*>(&Ws[k][col0 + j]);
                rw[j] = v.x; rw[j + 1] = v.y; rw[j + 2] = v.z; rw[j + 3] = v.w;
            }
#pragma unroll
            for (int i = 0; i < TM; ++i)
#pragma unroll
                for (int j = 0; j < TN; ++j)
                    acc[i][j] = fmaf(ra[i], rw[j], acc[i][j]);
        }
        __syncthreads();
    }

#pragma unroll
    for (int i = 0; i < TM; ++i) {
        int gr = bm + row0 + i;
        if (gr < M) {
            float rs = rowscale ? rowscale[gr] : 1.0f;
#pragma unroll
            for (int j = 0; j < TN; ++j) {
                int gc = bn + col0 + j;
                if (gc < N) {
                    float r = fmaf(acc[i][j], rs, bias[gc]);
                    if (RELU) r = fmaxf(r, 0.0f);
                    C[(size_t)gr * N + gc] = r;
                }
            }
        }
    }
}

// ------------------------- fused per-token attention ------------------------
// Block = 128 threads (warp m <-> modal m), TOK_PER_BLOCK tokens per block.
// smem: wq^T,wk^T,wv^T (3*4096) + xn(256) + q(256) + k(256) + attn(16) floats
#define ATTN_SMEM_FLOATS (3 * 4096 + 256 + 256 + 256 + 16)
#define ATTN_SMEM_BYTES  (ATTN_SMEM_FLOATS * 4)

__global__ void __launch_bounds__(128)
attn_kernel(const int* __restrict__ seq,
            const float* __restrict__ cemb,
            const float* __restrict__ temb,
            const float* __restrict__ cfemb,
            const float* __restrict__ idemb,
            const float* __restrict__ wq,
            const float* __restrict__ wk,
            const float* __restrict__ wv,
            float* __restrict__ out)
{
    extern __shared__ float dyn[];
    float* w_s  = dyn;                 // [3][64][64], transposed: w_s[mat][d][j]
    float* sxn  = dyn + 3 * 4096;      // [4][64]
    float* sq   = sxn + 256;           // [4][64]
    float* sk   = sq + 256;            // [4][64]
    float* satt = sk + 256;            // [4][4]

    const int t = threadIdx.x;
    const int warp = t >> 5, lane = t & 31;

    // stage transposed weights once
    for (int i = t; i < 4096; i += 128) {
        int j = i >> 6, d = i & 63;
        w_s[0 * 4096 + d * 64 + j] = wq[i];
        w_s[1 * 4096 + d * 64 + j] = wk[i];
        w_s[2 * 4096 + d * 64 + j] = wv[i];
    }
    __syncthreads();

    const float* tab = (warp == 0) ? cemb : (warp == 1) ? temb
                     : (warp == 2) ? cfemb : idemb;
    const int tok0 = blockIdx.x * TOK_PER_BLOCK;

    for (int it = 0; it < TOK_PER_BLOCK; ++it) {
        const int tok = tok0 + it;
        int idx = __ldg(&seq[tok]);
        if (idx >= NUM_ITEM) idx = 0;

        // ---- phase 1: gather, L2-norm, LayerNorm (warp m handles modal m)
        float2 e = *reinterpret_cast<const float2*>(tab + (size_t)idx * 64 + 2 * lane);
        float ss = fmaf(e.x, e.x, e.y * e.y);
#pragma unroll
        for (int o = 16; o > 0; o >>= 1) ss += __shfl_xor_sync(~0u, ss, o);
        float s = 1.0f / fmaxf(sqrtf(ss), 1e-12f);
        float v0 = e.x * s, v1 = e.y * s;
        float sm = v0 + v1;
#pragma unroll
        for (int o = 16; o > 0; o >>= 1) sm += __shfl_xor_sync(~0u, sm, o);
        float mu = sm * (1.0f / 64.0f);
        float d0 = v0 - mu, d1 = v1 - mu;
        float vv = fmaf(d0, d0, d1 * d1);
#pragma unroll
        for (int o = 16; o > 0; o >>= 1) vv += __shfl_xor_sync(~0u, vv, o);
        float inv = 1.0f / sqrtf(vv * (1.0f / 64.0f) + 1e-5f);
        *reinterpret_cast<float2*>(&sxn[warp * 64 + 2 * lane]) =
            make_float2(d0 * inv, d1 * inv);
        __syncthreads();

        // ---- phase 2: q, k for modal = warp  (each thread -> cols lane, lane+32)
        {
            const float* xr = sxn + warp * 64;
            float aq0 = 0.f, aq1 = 0.f, ak0 = 0.f, ak1 = 0.f;
#pragma unroll
            for (int d = 0; d < 64; ++d) {
                float xv = xr[d];
                aq0 = fmaf(xv, w_s[d * 64 + lane], aq0);
                aq1 = fmaf(xv, w_s[d * 64 + lane + 32], aq1);
                ak0 = fmaf(xv, w_s[4096 + d * 64 + lane], ak0);
                ak1 = fmaf(xv, w_s[4096 + d * 64 + lane + 32], ak1);
            }
            sq[warp * 64 + lane] = aq0; sq[warp * 64 + lane + 32] = aq1;
            sk[warp * 64 + lane] = ak0; sk[warp * 64 + lane + 32] = ak1;
        }
        __syncthreads();

        // ---- phase 3: scores + softmax (warp m -> row m of attn)
        {
            float2 q2 = *reinterpret_cast<const float2*>(&sq[warp * 64 + 2 * lane]);
            float sc0, sc1, sc2, sc3;
#pragma unroll
            for (int n = 0; n < 4; ++n) {
                float2 k2 = *reinterpret_cast<const float2*>(&sk[n * 64 + 2 * lane]);
                float p = fmaf(q2.x, k2.x, q2.y * k2.y);
#pragma unroll
                for (int o = 16; o > 0; o >>= 1) p += __shfl_xor_sync(~0u, p, o);
                p *= 0.125f;   // d^-0.5, d = 64
                if (n == 0) sc0 = p; else if (n == 1) sc1 = p;
                else if (n == 2) sc2 = p; else sc3 = p;
            }
            float mx = fmaxf(fmaxf(sc0, sc1), fmaxf(sc2, sc3));
            float e0x = expf(sc0 - mx), e1x = expf(sc1 - mx);
            float e2x = expf(sc2 - mx), e3x = expf(sc3 - mx);
            float rd = 1.0f / (e0x + e1x + e2x + e3x);
            if (lane == 0) {
                satt[warp * 4 + 0] = e0x * rd; satt[warp * 4 + 1] = e1x * rd;
                satt[warp * 4 + 2] = e2x * rd; satt[warp * 4 + 3] = e3x * rd;
            }
        }
        __syncthreads();

        // ---- phase 4: out = (sum_n c_n * xn_n) @ wv^T, c_n = mean_m attn[m][n]
        if (t < 64) {
            float c0 = 0.25f * (satt[0] + satt[4] + satt[8]  + satt[12]);
            float c1 = 0.25f * (satt[1] + satt[5] + satt[9]  + satt[13]);
            float c2 = 0.25f * (satt[2] + satt[6] + satt[10] + satt[14]);
            float c3 = 0.25f * (satt[3] + satt[7] + satt[11] + satt[15]);
            const float* wv_s = w_s + 2 * 4096;
            float acc = 0.f;
#pragma unroll
            for (int d = 0; d < 64; ++d) {
                float y = fmaf(c0, sxn[d],
                          fmaf(c1, sxn[64 + d],
                          fmaf(c2, sxn[128 + d], c3 * sxn[192 + d])));
                acc = fmaf(y, wv_s[d * 64 + t], acc);
            }
            out[(size_t)tok * 64 + t] = acc;
        }
        __syncthreads();
    }
}

// ------------------------- launch ------------------------------------------
extern "C" void kernel_launch(void* const* d_in, const int* in_sizes, int n_in,
                              void* d_out, int out_size)
{
    const int*   seq     = (const int*)d_in[0];
    const float* content = (const float*)d_in[1];
    const float* text    = (const float*)d_in[2];
    const float* cff     = (const float*)d_in[3];
    const float* idemb   = (const float*)d_in[4];
    const float* c_w1 = (const float*)d_in[5],  *c_b1 = (const float*)d_in[6];
    const float* c_w2 = (const float*)d_in[7],  *c_b2 = (const float*)d_in[8];
    const float* c_w3 = (const float*)d_in[9],  *c_b3 = (const float*)d_in[10];
    const float* t_w1 = (const float*)d_in[11], *t_b1 = (const float*)d_in[12];
    const float* t_w2 = (const float*)d_in[13], *t_b2 = (const float*)d_in[14];
    const float* t_w3 = (const float*)d_in[15], *t_b3 = (const float*)d_in[16];
    const float* cf_w = (const float*)d_in[17], *cf_b = (const float*)d_in[18];
    const float* wq   = (const float*)d_in[19];
    const float* wk   = (const float*)d_in[20];
    const float* wv   = (const float*)d_in[21];
    float* out = (float*)d_out;

    float *h1, *h2, *cemb, *temb, *cfemb, *invc, *invt;
    cudaGetSymbolAddress((void**)&h1,    g_h1);
    cudaGetSymbolAddress((void**)&h2,    g_h2);
    cudaGetSymbolAddress((void**)&cemb,  g_cemb);
    cudaGetSymbolAddress((void**)&temb,  g_temb);
    cudaGetSymbolAddress((void**)&cfemb, g_cfemb);
    cudaGetSymbolAddress((void**)&invc,  g_invc);
    cudaGetSymbolAddress((void**)&invt,  g_invt);

    const int M = NUM_ITEM;
    const int gy = (M + 127) / 128;   // 391

    // row norms
    rownorm_kernel<<<M, 128>>>(content, 1024, M, invc);
    rownorm_kernel<<<M, 128>>>(text, 768, M, invt);

    // content MLP
    sgemm_nt<128, 128, 16, 8, 8, true><<<dim3(1024 / 128, gy), 256>>>(
        M, 1024, 1024, content, c_w1, c_b1, invc, h1);
    sgemm_nt<128, 128, 16, 8, 8, true><<<dim3(256 / 128, gy), 256>>>(
        M, 256, 1024, h1, c_w2, c_b2, nullptr, h2);
    sgemm_nt<128, 64, 16, 8, 4, false><<<dim3(1, gy), 256>>>(
        M, 64, 256, h2, c_w3, c_b3, nullptr, cemb);

    // text MLP (reuse h1/h2)
    sgemm_nt<128, 128, 16, 8, 8, true><<<dim3(768 / 128, gy), 256>>>(
        M, 768, 768, text, t_w1, t_b1, invt, h1);
    sgemm_nt<128, 128, 16, 8, 8, true><<<dim3(256 / 128, gy), 256>>>(
        M, 256, 768, h1, t_w2, t_b2, nullptr, h2);
    sgemm_nt<128, 64, 16, 8, 4, false><<<dim3(1, gy), 256>>>(
        M, 64, 256, h2, t_w3, t_b3, nullptr, temb);

    // cf linear
    sgemm_nt<128, 64, 16, 8, 4, false><<<dim3(1, gy), 256>>>(
        M, 64, 64, cff, cf_w, cf_b, nullptr, cfemb);

    // fused gather + norm + attention
    cudaFuncSetAttribute(attn_kernel,
                         cudaFuncAttributeMaxDynamicSharedMemorySize,
                         ATTN_SMEM_BYTES);
    attn_kernel<<<N_TOKENS / TOK_PER_BLOCK, 128, ATTN_SMEM_BYTES>>>(
        seq, cemb, temb, cfemb, idemb, wq, wk, wv, out);
}

// round 4
// speedup vs baseline: 2.5958x; 2.5958x over previous
#include <cuda_runtime.h>
#include <cuda_bf16.h>
#include <stdint.h>
#include <math.h>

// ---------------------------------------------------------------------------
// DisentangledHierarchicalEncoder — tensor-core (mma.sync bf16 hi/lo split)
//
//   1. rownorm(content/text) -> inv row scales
//   2. split kernels: fp32 -> (hi,lo) bf16 pairs (row scale folded in for X)
//   3. GEMMs on tensor pipe: acc += Ah*Wh + Ah*Wl + Al*Wh  (fp32 accum)
//      epilogue: bias (+relu) then either fp32 out or bf16 hi/lo out (chained)
//   4. cf linear: small SIMT sgemm (0.2 G-MAC, negligible)
//   5. fused gather + l2norm + LayerNorm + attention (V never materialized)
// ---------------------------------------------------------------------------

#define NUM_ITEM   50000
#define N_TOKENS   (1024 * 50)
#define TOK_PER_BLOCK 32

// ------------------------- device scratch (static) -------------------------
__device__ __nv_bfloat16 g_ah[50000 * 1024];
__device__ __nv_bfloat16 g_al[50000 * 1024];
__device__ __nv_bfloat16 g_h1h[50000 * 1024];
__device__ __nv_bfloat16 g_h1l[50000 * 1024];
__device__ __nv_bfloat16 g_h2h[50000 * 256];
__device__ __nv_bfloat16 g_h2l[50000 * 256];
__device__ __nv_bfloat16 g_w1h[1024 * 1024];
__device__ __nv_bfloat16 g_w1l[1024 * 1024];
__device__ __nv_bfloat16 g_w2h[256 * 1024];
__device__ __nv_bfloat16 g_w2l[256 * 1024];
__device__ __nv_bfloat16 g_w3h[64 * 256];
__device__ __nv_bfloat16 g_w3l[64 * 256];
__device__ float g_cemb[50000 * 64];
__device__ float g_temb[50000 * 64];
__device__ float g_cfemb[50000 * 64];
__device__ float g_invc[50000];
__device__ float g_invt[50000];

// ------------------------- small PTX helpers --------------------------------
__device__ __forceinline__ void cp16(uint32_t dst, const void* src, int sz) {
    asm volatile("cp.async.cg.shared.global [%0], [%1], 16, %2;"
                 :: "r"(dst), "l"(src), "r"(sz));
}
__device__ __forceinline__ void ldm4(uint32_t& r0, uint32_t& r1,
                                     uint32_t& r2, uint32_t& r3, uint32_t a) {
    asm volatile("ldmatrix.sync.aligned.m8n8.x4.shared.b16 {%0,%1,%2,%3}, [%4];"
                 : "=r"(r0), "=r"(r1), "=r"(r2), "=r"(r3) : "r"(a));
}
__device__ __forceinline__ void mma_bf16(float* c, const uint32_t* a,
                                         const uint32_t* b) {
    asm volatile(
        "mma.sync.aligned.m16n8k16.row.col.f32.bf16.bf16.f32 "
        "{%0,%1,%2,%3}, {%4,%5,%6,%7}, {%8,%9}, {%0,%1,%2,%3};"
        : "+f"(c[0]), "+f"(c[1]), "+f"(c[2]), "+f"(c[3])
        : "r"(a[0]), "r"(a[1]), "r"(a[2]), "r"(a[3]), "r"(b[0]), "r"(b[1]));
}

// ------------------------- inverse L2 row norm ------------------------------
__global__ void rownorm_kernel(const float* __restrict__ X, int K, int M,
                               float* __restrict__ inv)
{
    int row = blockIdx.x;
    if (row >= M) return;
    const float4* x4 = reinterpret_cast<const float4*>(X + (size_t)row * K);
    int K4 = K >> 2;
    float s = 0.f;
    for (int i = threadIdx.x; i < K4; i += blockDim.x) {
        float4 v = x4[i];
        s += v.x * v.x + v.y * v.y + v.z * v.z + v.w * v.w;
    }
#pragma unroll
    for (int o = 16; o > 0; o >>= 1) s += __shfl_xor_sync(0xffffffffu, s, o);
    __shared__ float red[4];
    int w = threadIdx.x >> 5;
    if ((threadIdx.x & 31) == 0) red[w] = s;
    __syncthreads();
    if (threadIdx.x == 0) {
        float t = red[0] + red[1] + red[2] + red[3];
        inv[row] = 1.0f / fmaxf(sqrtf(t), 1e-12f);
    }
}

// ------------------------- fp32 -> bf16 hi/lo split -------------------------
// If inv != nullptr, scales each element by inv[element_index / K] first.
__global__ void split_kernel(const float* __restrict__ X,
                             const float* __restrict__ inv, int K, long n4,
                             __nv_bfloat16* __restrict__ hi,
                             __nv_bfloat16* __restrict__ lo)
{
    long i = blockIdx.x * (long)blockDim.x + threadIdx.x;
    if (i >= n4) return;
    float4 v = reinterpret_cast<const float4*>(X)[i];
    if (inv) {
        float s = inv[(i * 4) / K];   // K % 4 == 0 -> all 4 in same row
        v.x *= s; v.y *= s; v.z *= s; v.w *= s;
    }
    __nv_bfloat16 hx = __float2bfloat16(v.x), hy = __float2bfloat16(v.y);
    __nv_bfloat16 hz = __float2bfloat16(v.z), hw = __float2bfloat16(v.w);
    __nv_bfloat16 lx = __float2bfloat16(v.x - __bfloat162float(hx));
    __nv_bfloat16 ly = __float2bfloat16(v.y - __bfloat162float(hy));
    __nv_bfloat16 lz = __float2bfloat16(v.z - __bfloat162float(hz));
    __nv_bfloat16 lw = __float2bfloat16(v.w - __bfloat162float(hw));
    __nv_bfloat162 h0; h0.x = hx; h0.y = hy;
    __nv_bfloat162 h1; h1.x = hz; h1.y = hw;
    __nv_bfloat162 l0; l0.x = lx; l0.y = ly;
    __nv_bfloat162 l1; l1.x = lz; l1.y = lw;
    reinterpret_cast<__nv_bfloat162*>(hi)[2 * i]     = h0;
    reinterpret_cast<__nv_bfloat162*>(hi)[2 * i + 1] = h1;
    reinterpret_cast<__nv_bfloat162*>(lo)[2 * i]     = l0;
    reinterpret_cast<__nv_bfloat162*>(lo)[2 * i + 1] = l1;
}

// ------------------------- tensor-core GEMM ---------------------------------
// C = act( (Ah+Al) @ (Wh+Wl)^T + bias ),  A:[M,K] hi/lo bf16, W:[N,K] hi/lo.
// OUT_SPLIT: write bf16 hi/lo pair (for chained layers); else fp32.
template <int BN, int WARPS_M, int WARPS_N, bool RELU, bool OUT_SPLIT>
__global__ void __launch_bounds__(256)
mma_gemm(int M, int N, int K,
         const __nv_bfloat16* __restrict__ Ah, const __nv_bfloat16* __restrict__ Al,
         const __nv_bfloat16* __restrict__ Wh, const __nv_bfloat16* __restrict__ Wl,
         const float* __restrict__ bias,
         float* __restrict__ Cf,
         __nv_bfloat16* __restrict__ Ch, __nv_bfloat16* __restrict__ Cl)
{
    constexpr int BM = 128, BK = 32;
    constexpr int WM = BM / WARPS_M, WN = BN / WARPS_N;
    constexpr int MT = WM / 16, NT = WN / 8;
    constexpr int A_T = BM * 80;          // 80B padded rows (conflict-free)
    constexpr int W_T = BN * 80;
    constexpr int STAGE = 2 * A_T + 2 * W_T;
    constexpr int CH_A = BM * 4;          // 16B chunks per A tile
    constexpr int CH_W = BN * 4;
    constexpr int TOTAL = 2 * CH_A + 2 * CH_W;

    extern __shared__ char smem[];
    const uint32_t sb = (uint32_t)__cvta_generic_to_shared(smem);
    const int tid = threadIdx.x, lane = tid & 31, wid = tid >> 5;
    const int wm0 = (wid / WARPS_N) * WM;
    const int wn0 = (wid % WARPS_N) * WN;
    const int bm = blockIdx.y * BM, bn = blockIdx.x * BN;

    float acc[MT][NT][4];
#pragma unroll
    for (int m = 0; m < MT; ++m)
#pragma unroll
        for (int n = 0; n < NT; ++n)
#pragma unroll
            for (int j = 0; j < 4; ++j) acc[m][n][j] = 0.f;

    auto load_stage = [&](int s, int k0) {
        uint32_t d0 = sb + s * STAGE;
#pragma unroll
        for (int c = tid; c < TOTAL; c += 256) {
            const __nv_bfloat16* src; uint32_t dst; int sz = 16;
            if (c < CH_A) {
                int r = c >> 2, q = c & 3, g = bm + r;
                sz = g < M ? 16 : 0; if (g >= M) g = M - 1;
                src = Ah + (size_t)g * K + k0 + q * 8;
                dst = d0 + r * 80 + q * 16;
            } else if (c < 2 * CH_A) {
                int cc = c - CH_A, r = cc >> 2, q = cc & 3, g = bm + r;
                sz = g < M ? 16 : 0; if (g >= M) g = M - 1;
                src = Al + (size_t)g * K + k0 + q * 8;
                dst = d0 + A_T + r * 80 + q * 16;
            } else if (c < 2 * CH_A + CH_W) {
                int cc = c - 2 * CH_A, r = cc >> 2, q = cc & 3;
                src = Wh + (size_t)(bn + r) * K + k0 + q * 8;
                dst = d0 + 2 * A_T + r * 80 + q * 16;
            } else {
                int cc = c - 2 * CH_A - CH_W, r = cc >> 2, q = cc & 3;
                src = Wl + (size_t)(bn + r) * K + k0 + q * 8;
                dst = d0 + 2 * A_T + W_T + r * 80 + q * 16;
            }
            cp16(dst, src, sz);
        }
        asm volatile("cp.async.commit_group;");
    };

    const int nk = K / BK;
    load_stage(0, 0);

    for (int i = 0; i < nk; ++i) {
        if (i + 1 < nk) {
            load_stage((i + 1) & 1, (i + 1) * BK);
            asm volatile("cp.async.wait_group 1;");
        } else {
            asm volatile("cp.async.wait_group 0;");
        }
        __syncthreads();

        uint32_t aAh = sb + (i & 1) * STAGE;
        uint32_t aAl = aAh + A_T;
        uint32_t aWh = aAh + 2 * A_T;
        uint32_t aWl = aWh + W_T;

#pragma unroll
        for (int kh = 0; kh < 2; ++kh) {
            uint32_t bh[NT][2], bl[NT][2];
#pragma unroll
            for (int nn = 0; nn < NT; nn += 2) {
                int r = wn0 + nn * 8 + (lane & 7) + ((lane >> 4) << 3);
                uint32_t kb = ((lane >> 3) & 1) * 16 + kh * 32;
                ldm4(bh[nn][0], bh[nn][1], bh[nn + 1][0], bh[nn + 1][1],
                     aWh + r * 80 + kb);
                ldm4(bl[nn][0], bl[nn][1], bl[nn + 1][0], bl[nn + 1][1],
                     aWl + r * 80 + kb);
            }
#pragma unroll
            for (int mm = 0; mm < MT; ++mm) {
                int r = wm0 + mm * 16 + (lane & 7) + (((lane >> 3) & 1) << 3);
                uint32_t kb = ((lane >> 4) << 4) + kh * 32;
                uint32_t ah[4], al[4];
                ldm4(ah[0], ah[1], ah[2], ah[3], aAh + r * 80 + kb);
                ldm4(al[0], al[1], al[2], al[3], aAl + r * 80 + kb);
#pragma unroll
                for (int nn = 0; nn < NT; ++nn) {
                    mma_bf16(acc[mm][nn], ah, bh[nn]);
                    mma_bf16(acc[mm][nn], ah, bl[nn]);
                    mma_bf16(acc[mm][nn], al, bh[nn]);
                }
            }
        }
        __syncthreads();
    }

    // epilogue
#pragma unroll
    for (int mm = 0; mm < MT; ++mm) {
#pragma unroll
        for (int nn = 0; nn < NT; ++nn) {
            int col = bn + wn0 + nn * 8 + (lane & 3) * 2;
            float b0 = __ldg(bias + col), b1 = __ldg(bias + col + 1);
#pragma unroll
            for (int h = 0; h < 2; ++h) {
                int row = bm + wm0 + mm * 16 + (lane >> 2) + h * 8;
                if (row < M) {
                    float r0 = acc[mm][nn][2 * h + 0] + b0;
                    float r1 = acc[mm][nn][2 * h + 1] + b1;
                    if (RELU) { r0 = fmaxf(r0, 0.f); r1 = fmaxf(r1, 0.f); }
                    if (OUT_SPLIT) {
                        __nv_bfloat16 h0 = __float2bfloat16(r0);
                        __nv_bfloat16 h1 = __float2bfloat16(r1);
                        __nv_bfloat16 l0 = __float2bfloat16(r0 - __bfloat162float(h0));
                        __nv_bfloat16 l1 = __float2bfloat16(r1 - __bfloat162float(h1));
                        __nv_bfloat162 vh; vh.x = h0; vh.y = h1;
                        __nv_bfloat162 vl; vl.x = l0; vl.y = l1;
                        *reinterpret_cast<__nv_bfloat162*>(&Ch[(size_t)row * N + col]) = vh;
                        *reinterpret_cast<__nv_bfloat162*>(&Cl[(size_t)row * N + col]) = vl;
                    } else {
                        *reinterpret_cast<float2*>(&Cf[(size_t)row * N + col]) =
                            make_float2(r0, r1);
                    }
                }
            }
        }
    }
}

// ------------------------- small SIMT GEMM (cf layer only) ------------------
template <int BM, int BN, int BK, int TM, int TN, bool RELU>
__global__ void __launch_bounds__((BM / TM) * (BN / TN))
sgemm_nt(int M, int N, int K,
         const float* __restrict__ A,
         const float* __restrict__ W,
         const float* __restrict__ bias,
         const float* __restrict__ rowscale,
         float* __restrict__ C)
{
    constexpr int NT = (BM / TM) * (BN / TN);
    constexpr int KQ = BK / 4;
    __shared__ float As[BK][BM];
    __shared__ float Ws[BK][BN];

    const int tid  = threadIdx.x;
    const int bm   = blockIdx.y * BM;
    const int bn   = blockIdx.x * BN;
    const int row0 = (tid / (BN / TN)) * TM;
    const int col0 = (tid % (BN / TN)) * TN;

    float acc[TM][TN];
#pragma unroll
    for (int i = 0; i < TM; ++i)
#pragma unroll
        for (int j = 0; j < TN; ++j) acc[i][j] = 0.f;

    for (int k0 = 0; k0 < K; k0 += BK) {
        for (int i = tid; i < BM * KQ; i += NT) {
            int r = i / KQ, q = i % KQ;
            int gr = bm + r;
            float4 v = make_float4(0.f, 0.f, 0.f, 0.f);
            if (gr < M)
                v = *reinterpret_cast<const float4*>(&A[(size_t)gr * K + k0 + 4 * q]);
            As[4 * q + 0][r] = v.x; As[4 * q + 1][r] = v.y;
            As[4 * q + 2][r] = v.z; As[4 * q + 3][r] = v.w;
        }
        for (int i = tid; i < BN * KQ; i += NT) {
            int r = i / KQ, q = i % KQ;
            int gr = bn + r;
            float4 v = make_float4(0.f, 0.f, 0.f, 0.f);
            if (gr < N)
                v = *reinterpret_cast<const float4*>(&W[(size_t)gr * K + k0 + 4 * q]);
            Ws[4 * q + 0][r] = v.x; Ws[4 * q + 1][r] = v.y;
            Ws[4 * q + 2][r] = v.z; Ws[4 * q + 3][r] = v.w;
        }
        __syncthreads();
#pragma unroll
        for (int k = 0; k < BK; ++k) {
            float ra[TM], rw[TN];
#pragma unroll
            for (int i = 0; i < TM; i += 4) {
                float4 v = *reinterpret_cast<const float4*>(&As[k][row0 + i]);
                ra[i] = v.x; ra[i + 1] = v.y; ra[i + 2] = v.z; ra[i + 3] = v.w;
            }
#pragma unroll
            for (int j = 0; j < TN; j += 4) {
                float4 v = *reinterpret_cast<const float4*>(&Ws[k][col0 + j]);
                rw[j] = v.x; rw[j + 1] = v.y; rw[j + 2] = v.z; rw[j + 3] = v.w;
            }
#pragma unroll
            for (int i = 0; i < TM; ++i)
#pragma unroll
                for (int j = 0; j < TN; ++j)
                    acc[i][j] = fmaf(ra[i], rw[j], acc[i][j]);
        }
        __syncthreads();
    }

#pragma unroll
    for (int i = 0; i < TM; ++i) {
        int gr = bm + row0 + i;
        if (gr < M) {
            float rs = rowscale ? rowscale[gr] : 1.0f;
#pragma unroll
            for (int j = 0; j < TN; ++j) {
                int gc = bn + col0 + j;
                if (gc < N) {
                    float r = fmaf(acc[i][j], rs, bias[gc]);
                    if (RELU) r = fmaxf(r, 0.0f);
                    C[(size_t)gr * N + gc] = r;
                }
            }
        }
    }
}

// ------------------------- fused per-token attention ------------------------
#define ATTN_SMEM_FLOATS (3 * 4096 + 256 + 256 + 256 + 16)
#define ATTN_SMEM_BYTES  (ATTN_SMEM_FLOATS * 4)

__global__ void __launch_bounds__(128)
attn_kernel(const int* __restrict__ seq,
            const float* __restrict__ cemb,
            const float* __restrict__ temb,
            const float* __restrict__ cfemb,
            const float* __restrict__ idemb,
            const float* __restrict__ wq,
            const float* __restrict__ wk,
            const float* __restrict__ wv,
            float* __restrict__ out)
{
    extern __shared__ float dyn[];
    float* w_s  = dyn;                 // [3][64][64] transposed
    float* sxn  = dyn + 3 * 4096;
    float* sq   = sxn + 256;
    float* sk   = sq + 256;
    float* satt = sk + 256;

    const int t = threadIdx.x;
    const int warp = t >> 5, lane = t & 31;

    for (int i = t; i < 4096; i += 128) {
        int j = i >> 6, d = i & 63;
        w_s[0 * 4096 + d * 64 + j] = wq[i];
        w_s[1 * 4096 + d * 64 + j] = wk[i];
        w_s[2 * 4096 + d * 64 + j] = wv[i];
    }
    __syncthreads();

    const float* tab = (warp == 0) ? cemb : (warp == 1) ? temb
                     : (warp == 2) ? cfemb : idemb;
    const int tok0 = blockIdx.x * TOK_PER_BLOCK;

    for (int it = 0; it < TOK_PER_BLOCK; ++it) {
        const int tok = tok0 + it;
        int idx = __ldg(&seq[tok]);
        if (idx >= NUM_ITEM) idx = 0;

        float2 e = *reinterpret_cast<const float2*>(tab + (size_t)idx * 64 + 2 * lane);
        float ss = fmaf(e.x, e.x, e.y * e.y);
#pragma unroll
        for (int o = 16; o > 0; o >>= 1) ss += __shfl_xor_sync(~0u, ss, o);
        float s = 1.0f / fmaxf(sqrtf(ss), 1e-12f);
        float v0 = e.x * s, v1 = e.y * s;
        float sm = v0 + v1;
#pragma unroll
        for (int o = 16; o > 0; o >>= 1) sm += __shfl_xor_sync(~0u, sm, o);
        float mu = sm * (1.0f / 64.0f);
        float d0 = v0 - mu, d1 = v1 - mu;
        float vv = fmaf(d0, d0, d1 * d1);
#pragma unroll
        for (int o = 16; o > 0; o >>= 1) vv += __shfl_xor_sync(~0u, vv, o);
        float inv = 1.0f / sqrtf(vv * (1.0f / 64.0f) + 1e-5f);
        *reinterpret_cast<float2*>(&sxn[warp * 64 + 2 * lane]) =
            make_float2(d0 * inv, d1 * inv);
        __syncthreads();

        {
            const float* xr = sxn + warp * 64;
            float aq0 = 0.f, aq1 = 0.f, ak0 = 0.f, ak1 = 0.f;
#pragma unroll
            for (int d = 0; d < 64; ++d) {
                float xv = xr[d];
                aq0 = fmaf(xv, w_s[d * 64 + lane], aq0);
                aq1 = fmaf(xv, w_s[d * 64 + lane + 32], aq1);
                ak0 = fmaf(xv, w_s[4096 + d * 64 + lane], ak0);
                ak1 = fmaf(xv, w_s[4096 + d * 64 + lane + 32], ak1);
            }
            sq[warp * 64 + lane] = aq0; sq[warp * 64 + lane + 32] = aq1;
            sk[warp * 64 + lane] = ak0; sk[warp * 64 + lane + 32] = ak1;
        }
        __syncthreads();

        {
            float2 q2 = *reinterpret_cast<const float2*>(&sq[warp * 64 + 2 * lane]);
            float sc0, sc1, sc2, sc3;
#pragma unroll
            for (int n = 0; n < 4; ++n) {
                float2 k2 = *reinterpret_cast<const float2*>(&sk[n * 64 + 2 * lane]);
                float p = fmaf(q2.x, k2.x, q2.y * k2.y);
#pragma unroll
                for (int o = 16; o > 0; o >>= 1) p += __shfl_xor_sync(~0u, p, o);
                p *= 0.125f;
                if (n == 0) sc0 = p; else if (n == 1) sc1 = p;
                else if (n == 2) sc2 = p; else sc3 = p;
            }
            float mx = fmaxf(fmaxf(sc0, sc1), fmaxf(sc2, sc3));
            float e0x = expf(sc0 - mx), e1x = expf(sc1 - mx);
            float e2x = expf(sc2 - mx), e3x = expf(sc3 - mx);
            float rd = 1.0f / (e0x + e1x + e2x + e3x);
            if (lane == 0) {
                satt[warp * 4 + 0] = e0x * rd; satt[warp * 4 + 1] = e1x * rd;
                satt[warp * 4 + 2] = e2x * rd; satt[warp * 4 + 3] = e3x * rd;
            }
        }
        __syncthreads();

        if (t < 64) {
            float c0 = 0.25f * (satt[0] + satt[4] + satt[8]  + satt[12]);
            float c1 = 0.25f * (satt[1] + satt[5] + satt[9]  + satt[13]);
            float c2 = 0.25f * (satt[2] + satt[6] + satt[10] + satt[14]);
            float c3 = 0.25f * (satt[3] + satt[7] + satt[11] + satt[15]);
            const float* wv_s = w_s + 2 * 4096;
            float acc = 0.f;
#pragma unroll
            for (int d = 0; d < 64; ++d) {
                float y = fmaf(c0, sxn[d],
                          fmaf(c1, sxn[64 + d],
                          fmaf(c2, sxn[128 + d], c3 * sxn[192 + d])));
                acc = fmaf(y, wv_s[d * 64 + t], acc);
            }
            out[(size_t)tok * 64 + t] = acc;
        }
        __syncthreads();
    }
}

// ------------------------- launch ------------------------------------------
static inline int grid4(long n4) { return (int)((n4 + 255) / 256); }

extern "C" void kernel_launch(void* const* d_in, const int* in_sizes, int n_in,
                              void* d_out, int out_size)
{
    const int*   seq     = (const int*)d_in[0];
    const float* content = (const float*)d_in[1];
    const float* text    = (const float*)d_in[2];
    const float* cff     = (const float*)d_in[3];
    const float* idemb   = (const float*)d_in[4];
    const float* c_w1 = (const float*)d_in[5],  *c_b1 = (const float*)d_in[6];
    const float* c_w2 = (const float*)d_in[7],  *c_b2 = (const float*)d_in[8];
    const float* c_w3 = (const float*)d_in[9],  *c_b3 = (const float*)d_in[10];
    const float* t_w1 = (const float*)d_in[11], *t_b1 = (const float*)d_in[12];
    const float* t_w2 = (const float*)d_in[13], *t_b2 = (const float*)d_in[14];
    const float* t_w3 = (const float*)d_in[15], *t_b3 = (const float*)d_in[16];
    const float* cf_w = (const float*)d_in[17], *cf_b = (const float*)d_in[18];
    const float* wq   = (const float*)d_in[19];
    const float* wk   = (const float*)d_in[20];
    const float* wv   = (const float*)d_in[21];
    float* out = (float*)d_out;

    __nv_bfloat16 *ah, *al, *h1h, *h1l, *h2h, *h2l;
    __nv_bfloat16 *w1h, *w1l, *w2h, *w2l, *w3h, *w3l;
    float *cemb, *temb, *cfemb, *invc, *invt;
    cudaGetSymbolAddress((void**)&ah,  g_ah);   cudaGetSymbolAddress((void**)&al,  g_al);
    cudaGetSymbolAddress((void**)&h1h, g_h1h);  cudaGetSymbolAddress((void**)&h1l, g_h1l);
    cudaGetSymbolAddress((void**)&h2h, g_h2h);  cudaGetSymbolAddress((void**)&h2l, g_h2l);
    cudaGetSymbolAddress((void**)&w1h, g_w1h);  cudaGetSymbolAddress((void**)&w1l, g_w1l);
    cudaGetSymbolAddress((void**)&w2h, g_w2h);  cudaGetSymbolAddress((void**)&w2l, g_w2l);
    cudaGetSymbolAddress((void**)&w3h, g_w3h);  cudaGetSymbolAddress((void**)&w3l, g_w3l);
    cudaGetSymbolAddress((void**)&cemb,  g_cemb);
    cudaGetSymbolAddress((void**)&temb,  g_temb);
    cudaGetSymbolAddress((void**)&cfemb, g_cfemb);
    cudaGetSymbolAddress((void**)&invc,  g_invc);
    cudaGetSymbolAddress((void**)&invt,  g_invt);

    const int M = NUM_ITEM;
    const int gy = (M + 127) / 128;          // 391

    const int SMEM_BN128 = 2 * (2 * 128 * 80 + 2 * 128 * 80);   // 81920
    const int SMEM_BN64  = 2 * (2 * 128 * 80 + 2 * 64 * 80);    // 61440
    cudaFuncSetAttribute((const void*)mma_gemm<128, 2, 4, true, true>,
                         cudaFuncAttributeMaxDynamicSharedMemorySize, SMEM_BN128);
    cudaFuncSetAttribute((const void*)mma_gemm<64, 4, 2, false, false>,
                         cudaFuncAttributeMaxDynamicSharedMemorySize, SMEM_BN64);
    cudaFuncSetAttribute(attn_kernel,
                         cudaFuncAttributeMaxDynamicSharedMemorySize, ATTN_SMEM_BYTES);

    // row norms
    rownorm_kernel<<<M, 128>>>(content, 1024, M, invc);
    rownorm_kernel<<<M, 128>>>(text, 768, M, invt);

    // ---------------- content branch ----------------
    {
        long n4 = (long)M * 1024 / 4;
        split_kernel<<<grid4(n4), 256>>>(content, invc, 1024, n4, ah, al);
    }
    {
        long n4 = 1024L * 1024 / 4;
        split_kernel<<<grid4(n4), 256>>>(c_w1, nullptr, 1024, n4, w1h, w1l);
        n4 = 256L * 1024 / 4;
        split_kernel<<<grid4(n4), 256>>>(c_w2, nullptr, 1024, n4, w2h, w2l);
        n4 = 64L * 256 / 4;
        split_kernel<<<grid4(n4), 256>>>(c_w3, nullptr, 256, n4, w3h, w3l);
    }
    mma_gemm<128, 2, 4, true, true><<<dim3(8, gy), 256, SMEM_BN128>>>(
        M, 1024, 1024, ah, al, w1h, w1l, c_b1, nullptr, h1h, h1l);
    mma_gemm<128, 2, 4, true, true><<<dim3(2, gy), 256, SMEM_BN128>>>(
        M, 256, 1024, h1h, h1l, w2h, w2l, c_b2, nullptr, h2h, h2l);
    mma_gemm<64, 4, 2, false, false><<<dim3(1, gy), 256, SMEM_BN64>>>(
        M, 64, 256, h2h, h2l, w3h, w3l, c_b3, cemb, nullptr, nullptr);

    // ---------------- text branch ----------------
    {
        long n4 = (long)M * 768 / 4;
        split_kernel<<<grid4(n4), 256>>>(text, invt, 768, n4, ah, al);
    }
    {
        long n4 = 768L * 768 / 4;
        split_kernel<<<grid4(n4), 256>>>(t_w1, nullptr, 768, n4, w1h, w1l);
        n4 = 256L * 768 / 4;
        split_kernel<<<grid4(n4), 256>>>(t_w2, nullptr, 768, n4, w2h, w2l);
        n4 = 64L * 256 / 4;
        split_kernel<<<grid4(n4), 256>>>(t_w3, nullptr, 256, n4, w3h, w3l);
    }
    mma_gemm<128, 2, 4, true, true><<<dim3(6, gy), 256, SMEM_BN128>>>(
        M, 768, 768, ah, al, w1h, w1l, t_b1, nullptr, h1h, h1l);
    mma_gemm<128, 2, 4, true, true><<<dim3(2, gy), 256, SMEM_BN128>>>(
        M, 256, 768, h1h, h1l, w2h, w2l, t_b2, nullptr, h2h, h2l);
    mma_gemm<64, 4, 2, false, false><<<dim3(1, gy), 256, SMEM_BN64>>>(
        M, 64, 256, h2h, h2l, w3h, w3l, t_b3, temb, nullptr, nullptr);

    // cf linear (tiny)
    sgemm_nt<128, 64, 16, 8, 4, false><<<dim3(1, gy), 256>>>(
        M, 64, 64, cff, cf_w, cf_b, nullptr, cfemb);

    // fused gather + norm + attention
    attn_kernel<<<N_TOKENS / TOK_PER_BLOCK, 128, ATTN_SMEM_BYTES>>>(
        seq, cemb, temb, cfemb, idemb, wq, wk, wv, out);
}

// round 9
// speedup vs baseline: 2.9440x; 1.1341x over previous
#include <cuda_runtime.h>
#include <cuda_bf16.h>
#include <stdint.h>
#include <math.h>

// ---------------------------------------------------------------------------
// DisentangledHierarchicalEncoder — mma.sync bf16 hi/lo split (sm_103-safe)
//
//   1. normsplit: fused L2-rownorm + fp32->(hi,lo) bf16 split for X
//   2. split_kernel: weights -> (hi,lo) bf16
//   3. GEMMs: acc += Ah*Wh + Ah*Wl + Al*Wh (term-major ordering -> independent
//      accumulator chains), 2-stage cp.async, epilogue re-splits for chaining
//   4. cf linear: small SIMT sgemm
//   5. attention: warp-per-4-tokens, register q/k, no block barriers in loop
// ---------------------------------------------------------------------------

#define NUM_ITEM   50000
#define N_TOKENS   (1024 * 50)

// ------------------------- device scratch (static) -------------------------
__device__ __nv_bfloat16 g_ah[50000 * 1024];
__device__ __nv_bfloat16 g_al[50000 * 1024];
__device__ __nv_bfloat16 g_h1h[50000 * 1024];
__device__ __nv_bfloat16 g_h1l[50000 * 1024];
__device__ __nv_bfloat16 g_h2h[50000 * 256];
__device__ __nv_bfloat16 g_h2l[50000 * 256];
__device__ __nv_bfloat16 g_w1h[1024 * 1024];
__device__ __nv_bfloat16 g_w1l[1024 * 1024];
__device__ __nv_bfloat16 g_w2h[256 * 1024];
__device__ __nv_bfloat16 g_w2l[256 * 1024];
__device__ __nv_bfloat16 g_w3h[64 * 256];
__device__ __nv_bfloat16 g_w3l[64 * 256];
__device__ float g_cemb[50000 * 64];
__device__ float g_temb[50000 * 64];
__device__ float g_cfemb[50000 * 64];

// ------------------------- small PTX helpers --------------------------------
__device__ __forceinline__ void cp16(uint32_t dst, const void* src, int sz) {
    asm volatile("cp.async.cg.shared.global [%0], [%1], 16, %2;"
                 :: "r"(dst), "l"(src), "r"(sz));
}
__device__ __forceinline__ void ldm4(uint32_t& r0, uint32_t& r1,
                                     uint32_t& r2, uint32_t& r3, uint32_t a) {
    asm volatile("ldmatrix.sync.aligned.m8n8.x4.shared.b16 {%0,%1,%2,%3}, [%4];"
                 : "=r"(r0), "=r"(r1), "=r"(r2), "=r"(r3) : "r"(a));
}
__device__ __forceinline__ void mma_bf16(float* c, const uint32_t* a,
                                         const uint32_t* b) {
    asm volatile(
        "mma.sync.aligned.m16n8k16.row.col.f32.bf16.bf16.f32 "
        "{%0,%1,%2,%3}, {%4,%5,%6,%7}, {%8,%9}, {%0,%1,%2,%3};"
        : "+f"(c[0]), "+f"(c[1]), "+f"(c[2]), "+f"(c[3])
        : "r"(a[0]), "r"(a[1]), "r"(a[2]), "r"(a[3]), "r"(b[0]), "r"(b[1]));
}

// ------------------------- fused rownorm + hi/lo split (for X) --------------
// One block per row. Computes inv L2 norm, scales, splits to bf16 hi/lo.
__global__ void __launch_bounds__(128)
normsplit_kernel(const float* __restrict__ X, int K, int M,
                 __nv_bfloat16* __restrict__ hi, __nv_bfloat16* __restrict__ lo)
{
    int row = blockIdx.x;
    if (row >= M) return;
    const float4* x4 = reinterpret_cast<const float4*>(X + (size_t)row * K);
    const int K4 = K >> 2;
    float4 v[2];
    int cnt = 0;
    float s = 0.f;
    for (int i = threadIdx.x; i < K4; i += 128) {
        float4 t = x4[i];
        v[cnt++] = t;
        s += t.x * t.x + t.y * t.y + t.z * t.z + t.w * t.w;
    }
#pragma unroll
    for (int o = 16; o > 0; o >>= 1) s += __shfl_xor_sync(0xffffffffu, s, o);
    __shared__ float red[4];
    __shared__ float s_inv;
    int w = threadIdx.x >> 5;
    if ((threadIdx.x & 31) == 0) red[w] = s;
    __syncthreads();
    if (threadIdx.x == 0) {
        float t = red[0] + red[1] + red[2] + red[3];
        s_inv = 1.0f / fmaxf(sqrtf(t), 1e-12f);
    }
    __syncthreads();
    const float inv = s_inv;
    __nv_bfloat162* hrow = reinterpret_cast<__nv_bfloat162*>(hi + (size_t)row * K);
    __nv_bfloat162* lrow = reinterpret_cast<__nv_bfloat162*>(lo + (size_t)row * K);
    cnt = 0;
    for (int i = threadIdx.x; i < K4; i += 128) {
        float4 t = v[cnt++];
        t.x *= inv; t.y *= inv; t.z *= inv; t.w *= inv;
        __nv_bfloat16 hx = __float2bfloat16(t.x), hy = __float2bfloat16(t.y);
        __nv_bfloat16 hz = __float2bfloat16(t.z), hw = __float2bfloat16(t.w);
        __nv_bfloat162 h0; h0.x = hx; h0.y = hy;
        __nv_bfloat162 h1; h1.x = hz; h1.y = hw;
        __nv_bfloat162 l0, l1;
        l0.x = __float2bfloat16(t.x - __bfloat162float(hx));
        l0.y = __float2bfloat16(t.y - __bfloat162float(hy));
        l1.x = __float2bfloat16(t.z - __bfloat162float(hz));
        l1.y = __float2bfloat16(t.w - __bfloat162float(hw));
        hrow[2 * i] = h0; hrow[2 * i + 1] = h1;
        lrow[2 * i] = l0; lrow[2 * i + 1] = l1;
    }
}

// ------------------------- fp32 -> bf16 hi/lo split (weights) ---------------
__global__ void split_kernel(const float* __restrict__ X, long n4,
                             __nv_bfloat16* __restrict__ hi,
                             __nv_bfloat16* __restrict__ lo)
{
    long i = blockIdx.x * (long)blockDim.x + threadIdx.x;
    if (i >= n4) return;
    float4 v = reinterpret_cast<const float4*>(X)[i];
    __nv_bfloat16 hx = __float2bfloat16(v.x), hy = __float2bfloat16(v.y);
    __nv_bfloat16 hz = __float2bfloat16(v.z), hw = __float2bfloat16(v.w);
    __nv_bfloat162 h0; h0.x = hx; h0.y = hy;
    __nv_bfloat162 h1; h1.x = hz; h1.y = hw;
    __nv_bfloat162 l0, l1;
    l0.x = __float2bfloat16(v.x - __bfloat162float(hx));
    l0.y = __float2bfloat16(v.y - __bfloat162float(hy));
    l1.x = __float2bfloat16(v.z - __bfloat162float(hz));
    l1.y = __float2bfloat16(v.w - __bfloat162float(hw));
    reinterpret_cast<__nv_bfloat162*>(hi)[2 * i]     = h0;
    reinterpret_cast<__nv_bfloat162*>(hi)[2 * i + 1] = h1;
    reinterpret_cast<__nv_bfloat162*>(lo)[2 * i]     = l0;
    reinterpret_cast<__nv_bfloat162*>(lo)[2 * i + 1] = l1;
}

// ------------------------- tensor-core GEMM (mma.sync) ----------------------
// C = act( (Ah+Al)@(Wh+Wl)^T + bias ),  A:[M,K] hi/lo bf16, W:[N,K] hi/lo.
template <int BN, int WARPS_M, int WARPS_N, bool RELU, bool OUT_SPLIT>
__global__ void __launch_bounds__(256)
mma_gemm(int M, int N, int K,
         const __nv_bfloat16* __restrict__ Ah, const __nv_bfloat16* __restrict__ Al,
         const __nv_bfloat16* __restrict__ Wh, const __nv_bfloat16* __restrict__ Wl,
         const float* __restrict__ bias,
         float* __restrict__ Cf,
         __nv_bfloat16* __restrict__ Ch, __nv_bfloat16* __restrict__ Cl)
{
    constexpr int BM = 128, BK = 32;
    constexpr int WM = BM / WARPS_M, WN = BN / WARPS_N;
    constexpr int MT = WM / 16, NT = WN / 8;
    constexpr int A_T = BM * 80;          // 80B padded rows (conflict-free)
    constexpr int W_T = BN * 80;
    constexpr int STAGE = 2 * A_T + 2 * W_T;
    constexpr int CH_A = BM * 4;          // 16B chunks per A tile
    constexpr int CH_W = BN * 4;
    constexpr int TOTAL = 2 * CH_A + 2 * CH_W;

    extern __shared__ char smem[];
    const uint32_t sb = (uint32_t)__cvta_generic_to_shared(smem);
    const int tid = threadIdx.x, lane = tid & 31, wid = tid >> 5;
    const int wm0 = (wid / WARPS_N) * WM;
    const int wn0 = (wid % WARPS_N) * WN;
    const int bm = blockIdx.y * BM, bn = blockIdx.x * BN;

    float acc[MT][NT][4];
#pragma unroll
    for (int m = 0; m < MT; ++m)
#pragma unroll
        for (int n = 0; n < NT; ++n)
#pragma unroll
            for (int j = 0; j < 4; ++j) acc[m][n][j] = 0.f;

    auto load_stage = [&](int s, int k0) {
        uint32_t d0 = sb + s * STAGE;
#pragma unroll
        for (int c = tid; c < TOTAL; c += 256) {
            const __nv_bfloat16* src; uint32_t dst; int sz = 16;
            if (c < CH_A) {
                int r = c >> 2, q = c & 3, g = bm + r;
                sz = g < M ? 16 : 0; if (g >= M) g = M - 1;
                src = Ah + (size_t)g * K + k0 + q * 8;
                dst = d0 + r * 80 + q * 16;
            } else if (c < 2 * CH_A) {
                int cc = c - CH_A, r = cc >> 2, q = cc & 3, g = bm + r;
                sz = g < M ? 16 : 0; if (g >= M) g = M - 1;
                src = Al + (size_t)g * K + k0 + q * 8;
                dst = d0 + A_T + r * 80 + q * 16;
            } else if (c < 2 * CH_A + CH_W) {
                int cc = c - 2 * CH_A, r = cc >> 2, q = cc & 3;
                src = Wh + (size_t)(bn + r) * K + k0 + q * 8;
                dst = d0 + 2 * A_T + r * 80 + q * 16;
            } else {
                int cc = c - 2 * CH_A - CH_W, r = cc >> 2, q = cc & 3;
                src = Wl + (size_t)(bn + r) * K + k0 + q * 8;
                dst = d0 + 2 * A_T + W_T + r * 80 + q * 16;
            }
            cp16(dst, src, sz);
        }
        asm volatile("cp.async.commit_group;");
    };

    const int nk = K / BK;
    load_stage(0, 0);

    for (int i = 0; i < nk; ++i) {
        if (i + 1 < nk) {
            load_stage((i + 1) & 1, (i + 1) * BK);
            asm volatile("cp.async.wait_group 1;");
        } else {
            asm volatile("cp.async.wait_group 0;");
        }
        __syncthreads();

        uint32_t aAh = sb + (i & 1) * STAGE;
        uint32_t aAl = aAh + A_T;
        uint32_t aWh = aAh + 2 * A_T;
        uint32_t aWl = aWh + W_T;

#pragma unroll
        for (int kh = 0; kh < 2; ++kh) {
            uint32_t bh[NT][2], bl[NT][2];
#pragma unroll
            for (int nn = 0; nn < NT; nn += 2) {
                int r = wn0 + nn * 8 + (lane & 7) + ((lane >> 4) << 3);
                uint32_t kb = ((lane >> 3) & 1) * 16 + kh * 32;
                ldm4(bh[nn][0], bh[nn][1], bh[nn + 1][0], bh[nn + 1][1],
                     aWh + r * 80 + kb);
                ldm4(bl[nn][0], bl[nn][1], bl[nn + 1][0], bl[nn + 1][1],
                     aWl + r * 80 + kb);
            }
#pragma unroll
            for (int mm = 0; mm < MT; ++mm) {
                int r = wm0 + mm * 16 + (lane & 7) + (((lane >> 3) & 1) << 3);
                uint32_t kb = ((lane >> 4) << 4) + kh * 32;
                uint32_t ah[4], al[4];
                ldm4(ah[0], ah[1], ah[2], ah[3], aAh + r * 80 + kb);
                ldm4(al[0], al[1], al[2], al[3], aAl + r * 80 + kb);
                // term-major: consecutive MMAs hit different accumulators
#pragma unroll
                for (int nn = 0; nn < NT; ++nn) mma_bf16(acc[mm][nn], ah, bh[nn]);
#pragma unroll
                for (int nn = 0; nn < NT; ++nn) mma_bf16(acc[mm][nn], ah, bl[nn]);
#pragma unroll
                for (int nn = 0; nn < NT; ++nn) mma_bf16(acc[mm][nn], al, bh[nn]);
            }
        }
        __syncthreads();
    }

    // epilogue
#pragma unroll
    for (int mm = 0; mm < MT; ++mm) {
#pragma unroll
        for (int nn = 0; nn < NT; ++nn) {
            int col = bn + wn0 + nn * 8 + (lane & 3) * 2;
            float b0 = __ldg(bias + col), b1 = __ldg(bias + col + 1);
#pragma unroll
            for (int h = 0; h < 2; ++h) {
                int row = bm + wm0 + mm * 16 + (lane >> 2) + h * 8;
                if (row < M) {
                    float r0 = acc[mm][nn][2 * h + 0] + b0;
                    float r1 = acc[mm][nn][2 * h + 1] + b1;
                    if (RELU) { r0 = fmaxf(r0, 0.f); r1 = fmaxf(r1, 0.f); }
                    if (OUT_SPLIT) {
                        __nv_bfloat16 h0 = __float2bfloat16(r0);
                        __nv_bfloat16 h1 = __float2bfloat16(r1);
                        __nv_bfloat16 l0 = __float2bfloat16(r0 - __bfloat162float(h0));
                        __nv_bfloat16 l1 = __float2bfloat16(r1 - __bfloat162float(h1));
                        __nv_bfloat162 vh; vh.x = h0; vh.y = h1;
                        __nv_bfloat162 vl; vl.x = l0; vl.y = l1;
                        *reinterpret_cast<__nv_bfloat162*>(&Ch[(size_t)row * N + col]) = vh;
                        *reinterpret_cast<__nv_bfloat162*>(&Cl[(size_t)row * N + col]) = vl;
                    } else {
                        *reinterpret_cast<float2*>(&Cf[(size_t)row * N + col]) =
                            make_float2(r0, r1);
                    }
                }
            }
        }
    }
}

// ------------------------- small SIMT GEMM (cf layer only) ------------------
template <int BM, int BN, int BK, int TM, int TN, bool RELU>
__global__ void __launch_bounds__((BM / TM) * (BN / TN))
sgemm_nt(int M, int N, int K,
         const float* __restrict__ A,
         const float* __restrict__ W,
         const float* __restrict__ bias,
         float* __restrict__ C)
{
    constexpr int NT = (BM / TM) * (BN / TN);
    constexpr int KQ = BK / 4;
    __shared__ float As[BK][BM];
    __shared__ float Ws[BK][BN];

    const int tid  = threadIdx.x;
    const int bm   = blockIdx.y * BM;
    const int bn   = blockIdx.x * BN;
    const int row0 = (tid / (BN / TN)) * TM;
    const int col0 = (tid % (BN / TN)) * TN;

    float acc[TM][TN];
#pragma unroll
    for (int i = 0; i < TM; ++i)
#pragma unroll
        for (int j = 0; j < TN; ++j) acc[i][j] = 0.f;

    for (int k0 = 0; k0 < K; k0 += BK) {
        for (int i = tid; i < BM * KQ; i += NT) {
            int r = i / KQ, q = i % KQ;
            int gr = bm + r;
            float4 v = make_float4(0.f, 0.f, 0.f, 0.f);
            if (gr < M)
                v = *reinterpret_cast<const float4*>(&A[(size_t)gr * K + k0 + 4 * q]);
            As[4 * q + 0][r] = v.x; As[4 * q + 1][r] = v.y;
            As[4 * q + 2][r] = v.z; As[4 * q + 3][r] = v.w;
        }
        for (int i = tid; i < BN * KQ; i += NT) {
            int r = i / KQ, q = i % KQ;
            int gr = bn + r;
            float4 v = make_float4(0.f, 0.f, 0.f, 0.f);
            if (gr < N)
                v = *reinterpret_cast<const float4*>(&W[(size_t)gr * K + k0 + 4 * q]);
            Ws[4 * q + 0][r] = v.x; Ws[4 * q + 1][r] = v.y;
            Ws[4 * q + 2][r] = v.z; Ws[4 * q + 3][r] = v.w;
        }
        __syncthreads();
#pragma unroll
        for (int k = 0; k < BK; ++k) {
            float ra[TM], rw[TN];
#pragma unroll
            for (int i = 0; i < TM; i += 4) {
                float4 v = *reinterpret_cast<const float4*>(&As[k][row0 + i]);
                ra[i] = v.x; ra[i + 1] = v.y; ra[i + 2] = v.z; ra[i + 3] = v.w;
            }
#pragma unroll
            for (int j = 0; j < TN; j += 4) {
                float4 v = *reinterpret_cast<const float4*>(&Ws[k][col0 + j]);
                rw[j] = v.x; rw[j + 1] = v.y; rw[j + 2] = v.z; rw[j + 3] = v.w;
            }
#pragma unroll
            for (int i = 0; i < TM; ++i)
#pragma unroll
                for (int j = 0; j < TN; ++j)
                    acc[i][j] = fmaf(ra[i], rw[j], acc[i][j]);
        }
        __syncthreads();
    }

#pragma unroll
    for (int i = 0; i < TM; ++i) {
        int gr = bm + row0 + i;
        if (gr < M) {
#pragma unroll
            for (int j = 0; j < TN; ++j) {
                int gc = bn + col0 + j;
                if (gc < N)
                    C[(size_t)gr * N + gc] = acc[i][j] + bias[gc];
            }
        }
    }
}

// ------------------------- attention: warp-per-4-tokens ---------------------
// Block: 128 threads (4 warps). Each warp independently processes batches of
// 4 tokens; no __syncthreads inside the token loop. Weights staged once.
#define ATTN_TOK_ITERS 8                 // 4 warps * 4 tok * 8 = 128 tok/block
#define ATTN_SMEM_FLOATS (3 * 4096 + 4 * 4 * 4 * 64)
#define ATTN_SMEM_BYTES  (ATTN_SMEM_FLOATS * 4)

__global__ void __launch_bounds__(128)
attn_kernel(const int* __restrict__ seq,
            const float* __restrict__ cemb,
            const float* __restrict__ temb,
            const float* __restrict__ cfemb,
            const float* __restrict__ idemb,
            const float* __restrict__ wq,
            const float* __restrict__ wk,
            const float* __restrict__ wv,
            float* __restrict__ out)
{
    extern __shared__ float dyn[];
    float* w_s = dyn;                               // [3][64][64] transposed
    const int t = threadIdx.x;
    const int warp = t >> 5, lane = t & 31;
    float* xnw = dyn + 3 * 4096 + warp * 1024;      // [4 tok][4 modal][64]

    for (int i = t; i < 4096; i += 128) {
        int j = i >> 6, d = i & 63;
        w_s[0 * 4096 + d * 64 + j] = wq[i];
        w_s[1 * 4096 + d * 64 + j] = wk[i];
        w_s[2 * 4096 + d * 64 + j] = wv[i];
    }
    __syncthreads();

    const float* tabs[4] = {cemb, temb, cfemb, idemb};
    const float* wqs = w_s;
    const float* wks = w_s + 4096;
    const float* wvs = w_s + 2 * 4096;

    for (int it = 0; it < ATTN_TOK_ITERS; ++it) {
        const int tok0 = (blockIdx.x * 4 + warp) * (4 * ATTN_TOK_ITERS) + it * 4;

        int idx[4];
#pragma unroll
        for (int tt = 0; tt < 4; ++tt) {
            int v = __ldg(&seq[tok0 + tt]);
            idx[tt] = (v >= NUM_ITEM) ? 0 : v;
        }

        // ---- gather + l2norm + LayerNorm for 16 (token, modal) pairs
#pragma unroll
        for (int tm = 0; tm < 16; ++tm) {
            int tt = tm >> 2, m = tm & 3;
            float2 e = *reinterpret_cast<const float2*>(
                tabs[m] + (size_t)idx[tt] * 64 + 2 * lane);
            float ss = fmaf(e.x, e.x, e.y * e.y);
            float sm = e.x + e.y;
#pragma unroll
            for (int o = 16; o > 0; o >>= 1) {
                ss += __shfl_xor_sync(~0u, ss, o);
                sm += __shfl_xor_sync(~0u, sm, o);
            }
            float s  = 1.0f / fmaxf(sqrtf(ss), 1e-12f);
            float mu = s * sm * (1.0f / 64.0f);
            float var = s * s * ss * (1.0f / 64.0f) - mu * mu;
            float inv = 1.0f / sqrtf(var + 1e-5f);
            float d0 = (s * e.x - mu) * inv;
            float d1 = (s * e.y - mu) * inv;
            *reinterpret_cast<float2*>(&xnw[tm * 64 + 2 * lane]) =
                make_float2(d0, d1);
        }
        __syncwarp();

        // ---- q, k for all 16 (t,m): lane owns columns lane and lane+32
        float q0[16], q1[16], k0[16], k1[16];
#pragma unroll
        for (int tm = 0; tm < 16; ++tm) { q0[tm] = q1[tm] = k0[tm] = k1[tm] = 0.f; }
        for (int d = 0; d < 64; ++d) {
            float wqa = wqs[d * 64 + lane], wqb = wqs[d * 64 + lane + 32];
            float wka = wks[d * 64 + lane], wkb = wks[d * 64 + lane + 32];
#pragma unroll
            for (int tm = 0; tm < 16; ++tm) {
                float xv = xnw[tm * 64 + d];
                q0[tm] = fmaf(xv, wqa, q0[tm]);
                q1[tm] = fmaf(xv, wqb, q1[tm]);
                k0[tm] = fmaf(xv, wka, k0[tm]);
                k1[tm] = fmaf(xv, wkb, k1[tm]);
            }
        }

        // ---- scores + softmax -> pooled coefficients c[t][n]
        float cc[4][4];
#pragma unroll
        for (int tt = 0; tt < 4; ++tt) {
            float sc[4][4];
#pragma unroll
            for (int m = 0; m < 4; ++m)
#pragma unroll
                for (int n = 0; n < 4; ++n) {
                    float p = fmaf(q0[tt * 4 + m], k0[tt * 4 + n],
                                   q1[tt * 4 + m] * k1[tt * 4 + n]);
#pragma unroll
                    for (int o = 16; o > 0; o >>= 1) p += __shfl_xor_sync(~0u, p, o);
                    sc[m][n] = p * 0.125f;
                }
            float c0 = 0.f, c1 = 0.f, c2 = 0.f, c3 = 0.f;
#pragma unroll
            for (int m = 0; m < 4; ++m) {
                float mx = fmaxf(fmaxf(sc[m][0], sc[m][1]),
                                 fmaxf(sc[m][2], sc[m][3]));
                float e0 = expf(sc[m][0] - mx), e1 = expf(sc[m][1] - mx);
                float e2 = expf(sc[m][2] - mx), e3 = expf(sc[m][3] - mx);
                float rd = 1.0f / (e0 + e1 + e2 + e3);
                c0 = fmaf(e0, rd, c0); c1 = fmaf(e1, rd, c1);
                c2 = fmaf(e2, rd, c2); c3 = fmaf(e3, rd, c3);
            }
            cc[tt][0] = 0.25f * c0; cc[tt][1] = 0.25f * c1;
            cc[tt][2] = 0.25f * c2; cc[tt][3] = 0.25f * c3;
        }

        // ---- out[t] = (sum_n c_n * xn_n) @ wv^T  (cols lane, lane+32)
        float o0[4] = {0.f, 0.f, 0.f, 0.f}, o1[4] = {0.f, 0.f, 0.f, 0.f};
        for (int d = 0; d < 64; ++d) {
            float wva = wvs[d * 64 + lane], wvb = wvs[d * 64 + lane + 32];
#pragma unroll
            for (int tt = 0; tt < 4; ++tt) {
                float z = fmaf(cc[tt][0], xnw[(tt * 4 + 0) * 64 + d],
                          fmaf(cc[tt][1], xnw[(tt * 4 + 1) * 64 + d],
                          fmaf(cc[tt][2], xnw[(tt * 4 + 2) * 64 + d],
                               cc[tt][3] * xnw[(tt * 4 + 3) * 64 + d])));
                o0[tt] = fmaf(z, wva, o0[tt]);
                o1[tt] = fmaf(z, wvb, o1[tt]);
            }
        }
#pragma unroll
        for (int tt = 0; tt < 4; ++tt) {
            out[(size_t)(tok0 + tt) * 64 + lane]      = o0[tt];
            out[(size_t)(tok0 + tt) * 64 + lane + 32] = o1[tt];
        }
        __syncwarp();
    }
}

// ------------------------- launch ------------------------------------------
static inline int grid4(long n4) { return (int)((n4 + 255) / 256); }

extern "C" void kernel_launch(void* const* d_in, const int* in_sizes, int n_in,
                              void* d_out, int out_size)
{
    const int*   seq     = (const int*)d_in[0];
    const float* content = (const float*)d_in[1];
    const float* text    = (const float*)d_in[2];
    const float* cff     = (const float*)d_in[3];
    const float* idemb   = (const float*)d_in[4];
    const float* c_w1 = (const float*)d_in[5],  *c_b1 = (const float*)d_in[6];
    const float* c_w2 = (const float*)d_in[7],  *c_b2 = (const float*)d_in[8];
    const float* c_w3 = (const float*)d_in[9],  *c_b3 = (const float*)d_in[10];
    const float* t_w1 = (const float*)d_in[11], *t_b1 = (const float*)d_in[12];
    const float* t_w2 = (const float*)d_in[13], *t_b2 = (const float*)d_in[14];
    const float* t_w3 = (const float*)d_in[15], *t_b3 = (const float*)d_in[16];
    const float* cf_w = (const float*)d_in[17], *cf_b = (const float*)d_in[18];
    const float* wq   = (const float*)d_in[19];
    const float* wk   = (const float*)d_in[20];
    const float* wv   = (const float*)d_in[21];
    float* out = (float*)d_out;

    __nv_bfloat16 *ah, *al, *h1h, *h1l, *h2h, *h2l;
    __nv_bfloat16 *w1h, *w1l, *w2h, *w2l, *w3h, *w3l;
    float *cemb, *temb, *cfemb;
    cudaGetSymbolAddress((void**)&ah,  g_ah);   cudaGetSymbolAddress((void**)&al,  g_al);
    cudaGetSymbolAddress((void**)&h1h, g_h1h);  cudaGetSymbolAddress((void**)&h1l, g_h1l);
    cudaGetSymbolAddress((void**)&h2h, g_h2h);  cudaGetSymbolAddress((void**)&h2l, g_h2l);
    cudaGetSymbolAddress((void**)&w1h, g_w1h);  cudaGetSymbolAddress((void**)&w1l, g_w1l);
    cudaGetSymbolAddress((void**)&w2h, g_w2h);  cudaGetSymbolAddress((void**)&w2l, g_w2l);
    cudaGetSymbolAddress((void**)&w3h, g_w3h);  cudaGetSymbolAddress((void**)&w3l, g_w3l);
    cudaGetSymbolAddress((void**)&cemb,  g_cemb);
    cudaGetSymbolAddress((void**)&temb,  g_temb);
    cudaGetSymbolAddress((void**)&cfemb, g_cfemb);

    const int M = NUM_ITEM;
    const int gy = (M + 127) / 128;   // 391

    const int SMEM_BN128 = 2 * (2 * 128 * 80 + 2 * 128 * 80);   // 81920
    const int SMEM_BN64  = 2 * (2 * 128 * 80 + 2 * 64 * 80);    // 61440
    cudaFuncSetAttribute((const void*)mma_gemm<128, 2, 4, true, true>,
                         cudaFuncAttributeMaxDynamicSharedMemorySize, SMEM_BN128);
    cudaFuncSetAttribute((const void*)mma_gemm<64, 4, 2, false, false>,
                         cudaFuncAttributeMaxDynamicSharedMemorySize, SMEM_BN64);
    cudaFuncSetAttribute(attn_kernel,
                         cudaFuncAttributeMaxDynamicSharedMemorySize, ATTN_SMEM_BYTES);

    // ---------------- content branch ----------------
    normsplit_kernel<<<M, 128>>>(content, 1024, M, ah, al);
    split_kernel<<<grid4(1024L * 1024 / 4), 256>>>(c_w1, 1024L * 1024 / 4, w1h, w1l);
    split_kernel<<<grid4(256L * 1024 / 4), 256>>>(c_w2, 256L * 1024 / 4, w2h, w2l);
    split_kernel<<<grid4(64L * 256 / 4), 256>>>(c_w3, 64L * 256 / 4, w3h, w3l);

    mma_gemm<128, 2, 4, true, true><<<dim3(8, gy), 256, SMEM_BN128>>>(
        M, 1024, 1024, ah, al, w1h, w1l, c_b1, nullptr, h1h, h1l);
    mma_gemm<128, 2, 4, true, true><<<dim3(2, gy), 256, SMEM_BN128>>>(
        M, 256, 1024, h1h, h1l, w2h, w2l, c_b2, nullptr, h2h, h2l);
    mma_gemm<64, 4, 2, false, false><<<dim3(1, gy), 256, SMEM_BN64>>>(
        M, 64, 256, h2h, h2l, w3h, w3l, c_b3, cemb, nullptr, nullptr);

    // ---------------- text branch ----------------
    normsplit_kernel<<<M, 128>>>(text, 768, M, ah, al);
    split_kernel<<<grid4(768L * 768 / 4), 256>>>(t_w1, 768L * 768 / 4, w1h, w1l);
    split_kernel<<<grid4(256L * 768 / 4), 256>>>(t_w2, 256L * 768 / 4, w2h, w2l);
    split_kernel<<<grid4(64L * 256 / 4), 256>>>(t_w3, 64L * 256 / 4, w3h, w3l);

    mma_gemm<128, 2, 4, true, true><<<dim3(6, gy), 256, SMEM_BN128>>>(
        M, 768, 768, ah, al, w1h, w1l, t_b1, nullptr, h1h, h1l);
    mma_gemm<128, 2, 4, true, true><<<dim3(2, gy), 256, SMEM_BN128>>>(
        M, 256, 768, h1h, h1l, w2h, w2l, t_b2, nullptr, h2h, h2l);
    mma_gemm<64, 4, 2, false, false><<<dim3(1, gy), 256, SMEM_BN64>>>(
        M, 64, 256, h2h, h2l, w3h, w3l, t_b3, temb, nullptr, nullptr);

    // cf linear (tiny)
    sgemm_nt<128, 64, 16, 8, 4, false><<<dim3(1, gy), 256>>>(
        M, 64, 64, cff, cf_w, cf_b, cfemb);

    // fused gather + norm + attention (warp-per-4-tokens)
    attn_kernel<<<N_TOKENS / 128, 128, ATTN_SMEM_BYTES>>>(
        seq, cemb, temb, cfemb, idemb, wq, wk, wv, out);
}